// round 2
// baseline (speedup 1.0000x reference)
#include <cuda_runtime.h>
#include <cstdint>

#define WS        7
#define NTOK      49
#define CH        64
#define CQ        8
#define HWDIM     224
#define XS_STRIDE 68     // pad: 4t+c bank pattern -> conflict-free, 16B-aligned rows
#define QK_STRIDE 9      // odd stride -> conflict-free along tokens
#define ATT_STRIDE 51    // gcd(51,32)=1 -> conflict-free softmax row access
#define NTHREADS  128

// Dynamic smem layout (floats), each segment rounded to 4 floats for float4 alignment
#define OFF_XS   0
#define SZ_XS    (NTOK * XS_STRIDE)        // 3332
#define OFF_WVT  (OFF_XS + SZ_XS)          // 3332
#define SZ_WVT   (CH * CH)                 // 4096
#define OFF_WQT  (OFF_WVT + SZ_WVT)        // 7428
#define SZ_WQT   (CH * CQ)                 // 512
#define OFF_WKT  (OFF_WQT + SZ_WQT)        // 7940
#define SZ_WKT   (CH * CQ)                 // 512
#define OFF_QS   (OFF_WKT + SZ_WKT)        // 8452
#define SZ_QS    444                       // 49*9=441 -> 444
#define OFF_KS   (OFF_QS + SZ_QS)          // 8896
#define SZ_KS    444
#define OFF_ATT  (OFF_KS + SZ_KS)          // 9340
#define SZ_ATT   2500                      // 49*51=2499 -> 2500
#define OFF_VS   (OFF_ATT + SZ_ATT)        // 11840 (mult of 4 -> float4 OK)
#define SZ_VS    (NTOK * CH)               // 3136
#define SMEM_FLOATS (OFF_VS + SZ_VS)       // 14976
#define SMEM_BYTES  (SMEM_FLOATS * 4)      // 59904

__global__ void __launch_bounds__(NTHREADS)
lattn_kernel(const float* __restrict__ x,
             const float* __restrict__ Wq, const float* __restrict__ bq,
             const float* __restrict__ Wk, const float* __restrict__ bk,
             const float* __restrict__ Wv, const float* __restrict__ bv,
             const float* __restrict__ gamma,
             float* __restrict__ out)
{
    extern __shared__ float sm[];
    float* xs  = sm + OFF_XS;    // [49][68]  x window (later holds final output)
    float* wvt = sm + OFF_WVT;   // [64][64]  Wv transposed: wvt[c][o]
    float* wqt = sm + OFF_WQT;   // [64][8]
    float* wkt = sm + OFF_WKT;   // [64][8]
    float* qs  = sm + OFF_QS;    // [49][9]
    float* ks  = sm + OFF_KS;    // [49][9]
    float* att = sm + OFF_ATT;   // [49][51]
    float* vs  = sm + OFF_VS;    // [49][64]

    const int tid = threadIdx.x;
    const int blk = blockIdx.x;
    const int b  = blk >> 10;          // blk / 1024
    const int l  = blk & 1023;
    const int wh = l >> 5, ww = l & 31;
    const int h0 = wh * WS, w0 = ww * WS;

    const float* xb = x + (size_t)b * CH * HWDIM * HWDIM;

    // ---- Phase 0: load x window (lane-contiguous in w for coalescing) + weights
    #pragma unroll
    for (int idx = tid; idx < CH * NTOK; idx += NTHREADS) {
        int c = idx / NTOK;
        int t = idx - c * NTOK;
        int ph = t / WS, pw = t - ph * WS;
        xs[t * XS_STRIDE + c] = __ldg(&xb[((size_t)c * HWDIM + (h0 + ph)) * HWDIM + (w0 + pw)]);
    }
    for (int idx = tid; idx < CH * CH; idx += NTHREADS) {
        int o = idx >> 6, c = idx & 63;
        wvt[c * CH + o] = __ldg(&Wv[idx]);
    }
    for (int idx = tid; idx < CQ * CH; idx += NTHREADS) {
        int o = idx >> 6, c = idx & 63;
        wqt[c * CQ + o] = __ldg(&Wq[idx]);
        wkt[c * CQ + o] = __ldg(&Wk[idx]);
    }
    __syncthreads();

    // ---- Phase 1a: V projection, register tile 7 tokens x 4 out-channels (112 threads)
    if (tid < 112) {
        const int og = tid & 15, tg = tid >> 4;
        const int o0 = og * 4, t0 = tg * WS;
        float acc[7][4];
        #pragma unroll
        for (int i = 0; i < 7; i++)
            #pragma unroll
            for (int j = 0; j < 4; j++) acc[i][j] = 0.0f;

        #pragma unroll 4
        for (int c = 0; c < CH; c++) {
            float4 w = *reinterpret_cast<const float4*>(wvt + c * CH + o0);
            #pragma unroll
            for (int i = 0; i < 7; i++) {
                float xv = xs[(t0 + i) * XS_STRIDE + c];
                acc[i][0] = fmaf(xv, w.x, acc[i][0]);
                acc[i][1] = fmaf(xv, w.y, acc[i][1]);
                acc[i][2] = fmaf(xv, w.z, acc[i][2]);
                acc[i][3] = fmaf(xv, w.w, acc[i][3]);
            }
        }
        float b0 = __ldg(&bv[o0 + 0]), b1 = __ldg(&bv[o0 + 1]);
        float b2 = __ldg(&bv[o0 + 2]), b3 = __ldg(&bv[o0 + 3]);
        #pragma unroll
        for (int i = 0; i < 7; i++) {
            float4 r;
            r.x = acc[i][0] + b0; r.y = acc[i][1] + b1;
            r.z = acc[i][2] + b2; r.w = acc[i][3] + b3;
            *reinterpret_cast<float4*>(vs + (t0 + i) * CH + o0) = r;
        }
    }

    // ---- Phase 1b: Q and K projections (784 small dots, all 128 threads)
    for (int idx = tid; idx < 2 * NTOK * CQ; idx += NTHREADS) {
        int which = (idx >= NTOK * CQ);
        int r = which ? (idx - NTOK * CQ) : idx;
        int t = r >> 3, o = r & 7;
        const float* wt = which ? wkt : wqt;
        const float* xr = xs + t * XS_STRIDE;
        float s = 0.0f;
        #pragma unroll 8
        for (int c = 0; c < CH; c++) s = fmaf(xr[c], wt[c * CQ + o], s);
        s += which ? __ldg(&bk[o]) : __ldg(&bq[o]);
        (which ? ks : qs)[t * QK_STRIDE + o] = s;
    }
    __syncthreads();

    // ---- Phase 2: logits  att[n][m] = <q_n, k_m>  (dim 8)
    for (int idx = tid; idx < NTOK * NTOK; idx += NTHREADS) {
        int n = idx / NTOK;
        int m = idx - n * NTOK;
        const float* qr = qs + n * QK_STRIDE;
        const float* kr = ks + m * QK_STRIDE;
        float s = 0.0f;
        #pragma unroll
        for (int c = 0; c < CQ; c++) s = fmaf(qr[c], kr[c], s);
        att[n * ATT_STRIDE + m] = s;
    }
    __syncthreads();

    // ---- Phase 3: softmax over keys (one thread per row)
    if (tid < NTOK) {
        float* row = att + tid * ATT_STRIDE;
        float mx = row[0];
        #pragma unroll 7
        for (int m = 1; m < NTOK; m++) mx = fmaxf(mx, row[m]);
        float s = 0.0f;
        #pragma unroll 7
        for (int m = 0; m < NTOK; m++) {
            float e = __expf(row[m] - mx);
            row[m] = e;
            s += e;
        }
        float rinv = 1.0f / s;
        #pragma unroll 7
        for (int m = 0; m < NTOK; m++) row[m] *= rinv;
    }
    __syncthreads();

    // ---- Phase 4: out = att @ V, fused residual into xs (in place)
    const float g = __ldg(gamma);
    if (tid < 112) {
        const int og = tid & 15, tg = tid >> 4;
        const int c0 = og * 4, n0 = tg * WS;
        float acc[7][4];
        #pragma unroll
        for (int i = 0; i < 7; i++)
            #pragma unroll
            for (int j = 0; j < 4; j++) acc[i][j] = 0.0f;

        #pragma unroll 4
        for (int m = 0; m < NTOK; m++) {
            float4 vv = *reinterpret_cast<const float4*>(vs + m * CH + c0);
            #pragma unroll
            for (int i = 0; i < 7; i++) {
                float a = att[(n0 + i) * ATT_STRIDE + m];
                acc[i][0] = fmaf(a, vv.x, acc[i][0]);
                acc[i][1] = fmaf(a, vv.y, acc[i][1]);
                acc[i][2] = fmaf(a, vv.z, acc[i][2]);
                acc[i][3] = fmaf(a, vv.w, acc[i][3]);
            }
        }
        #pragma unroll
        for (int i = 0; i < 7; i++) {
            float* xr = xs + (n0 + i) * XS_STRIDE + c0;
            float4 xv = *reinterpret_cast<const float4*>(xr);
            xv.x = fmaf(g, acc[i][0], xv.x);
            xv.y = fmaf(g, acc[i][1], xv.y);
            xv.z = fmaf(g, acc[i][2], xv.z);
            xv.w = fmaf(g, acc[i][3], xv.w);
            *reinterpret_cast<float4*>(xr) = xv;
        }
    }
    __syncthreads();

    // ---- Phase 5: coalesced-ish store (lane-contiguous in w; L2 merges partial sectors)
    float* ob = out + (size_t)b * CH * HWDIM * HWDIM;
    #pragma unroll
    for (int idx = tid; idx < CH * NTOK; idx += NTHREADS) {
        int c = idx / NTOK;
        int t = idx - c * NTOK;
        int ph = t / WS, pw = t - ph * WS;
        ob[((size_t)c * HWDIM + (h0 + ph)) * HWDIM + (w0 + pw)] = xs[t * XS_STRIDE + c];
    }
}

extern "C" void kernel_launch(void* const* d_in, const int* in_sizes, int n_in,
                              void* d_out, int out_size)
{
    const float* x     = (const float*)d_in[0];
    const float* Wq    = (const float*)d_in[1];
    const float* bq    = (const float*)d_in[2];
    const float* Wk    = (const float*)d_in[3];
    const float* bk    = (const float*)d_in[4];
    const float* Wv    = (const float*)d_in[5];
    const float* bv    = (const float*)d_in[6];
    const float* gamma = (const float*)d_in[7];
    float* out = (float*)d_out;

    cudaFuncSetAttribute(lattn_kernel, cudaFuncAttributeMaxDynamicSharedMemorySize, SMEM_BYTES);

    const int B = 16;
    const int nwin = (HWDIM / WS) * (HWDIM / WS);  // 1024
    dim3 grid(B * nwin);
    lattn_kernel<<<grid, NTHREADS, SMEM_BYTES>>>(x, Wq, bq, Wk, bk, Wv, bv, gamma, out);
}

// round 3
// speedup vs baseline: 1.1512x; 1.1512x over previous
#include <cuda_runtime.h>
#include <cstdint>

typedef unsigned long long u64;

#define NTHREADS 256
#define WS 7
#define NTOK 49
#define CH 64
#define CQ 8
#define HWDIM 224
#define XT_STRIDE 58
#define AT_STRIDE 58
#define OS_STRIDE 66
#define WCT_STRIDE 80
#define NOUT 80

// ---- smem layout (floats) ----
#define OFF_WCT   0
#define SZ_WCT    (CH*WCT_STRIDE)          // 5120
#define OFF_XT0   (OFF_WCT + SZ_WCT)       // 5120
#define SZ_XT     (CH*XT_STRIDE)           // 3712
#define OFF_XT1   (OFF_XT0 + SZ_XT)        // 8832
#define OFF_POOL0 (OFF_XT1 + SZ_XT)        // 12544
#define SZ_POOL   3744
#define OFF_QS0   (OFF_POOL0)              // 448 floats
#define OFF_KS0   (OFF_POOL0 + 448)
#define OFF_AT0   (OFF_POOL0 + 896)        // 49*58=2842 <= 2848
#define OFF_POOL1 (OFF_POOL0 + SZ_POOL)    // 16288
#define OFF_QS1   (OFF_POOL1)
#define OFF_KS1   (OFF_POOL1 + 448)
#define OFF_AT1   (OFF_POOL1 + 896)
#define OFF_VS0   (OFF_POOL1 + SZ_POOL)    // 20032
#define SZ_VS     (NTOK*CH)                // 3136
#define OFF_VS1   (OFF_VS0 + SZ_VS)        // 23168
#define SMEM_FLOATS (OFF_VS1 + SZ_VS)      // 26304
#define SMEM_BYTES  (SMEM_FLOATS*4)        // 105216

// phase-0 raw weight staging overlays the two pools (5200 <= 7488)
#define OFF_WRV   (OFF_POOL0)
#define OFF_WRQ   (OFF_POOL0 + 4160)
#define OFF_WRK   (OFF_WRQ + 520)

__device__ __forceinline__ u64 f2swap(u64 v){
    u64 r;
    asm("{\n\t.reg .b32 l,h;\n\tmov.b64 {l,h}, %1;\n\tmov.b64 %0, {h,l};\n\t}"
        : "=l"(r) : "l"(v));
    return r;
}
__device__ __forceinline__ void ffma2(u64 &d, u64 a, u64 b){
    asm("fma.rn.f32x2 %0, %1, %2, %0;" : "+l"(d) : "l"(a), "l"(b));
}
__device__ __forceinline__ float f2lo(u64 v){ return __int_as_float((unsigned)(v & 0xffffffffull)); }
__device__ __forceinline__ float f2hi(u64 v){ return __int_as_float((unsigned)(v >> 32)); }

__global__ void __launch_bounds__(NTHREADS, 2)
lattn_kernel(const float* __restrict__ x,
             const float* __restrict__ Wq, const float* __restrict__ bq,
             const float* __restrict__ Wk, const float* __restrict__ bk,
             const float* __restrict__ Wv, const float* __restrict__ bv,
             const float* __restrict__ gamma,
             float* __restrict__ out)
{
    extern __shared__ float sm[];
    const int tid = threadIdx.x;
    const int blk = blockIdx.x;          // 16 b * 32 wh * 16 wpair
    const int b   = blk >> 9;
    const int rem = blk & 511;
    const int wh  = rem >> 4;
    const int wp  = rem & 15;
    const int h0  = wh * WS;
    const int w0  = wp * 14;

    const float* xb = x + (size_t)b * CH * HWDIM * HWDIM;

    // ===== Phase 0: loads =====
    // x -> xT[win][c][t], 14 contiguous floats per (c,row) global read
    for (int idx = tid; idx < CH * WS * 14; idx += NTHREADS) {
        int c  = idx / 98;
        int r  = idx - c * 98;
        int ph = r / 14;
        int pw = r - ph * 14;
        int win = (pw >= 7);
        int t  = ph * 7 + (pw - win * 7);
        float v = __ldg(&xb[((size_t)c * HWDIM + (h0 + ph)) * HWDIM + (w0 + pw)]);
        sm[(win ? OFF_XT1 : OFF_XT0) + c * XT_STRIDE + t] = v;
    }
    // zero token padding t = 49..55
    for (int idx = tid; idx < CH * 14; idx += NTHREADS) {
        int win = idx & 1;
        int r   = idx >> 1;
        int c   = r / 7;
        int j   = r - c * 7;
        sm[(win ? OFF_XT1 : OFF_XT0) + c * XT_STRIDE + 49 + j] = 0.0f;
    }
    // stage raw weights [o][c] (stride 65)
    for (int idx = tid; idx < CH * CH; idx += NTHREADS) {
        int o = idx >> 6, c = idx & 63;
        sm[OFF_WRV + o * 65 + c] = __ldg(&Wv[idx]);
    }
    for (int idx = tid; idx < CQ * CH; idx += NTHREADS) {
        int o = idx >> 6, c = idx & 63;
        sm[OFF_WRQ + o * 65 + c] = __ldg(&Wq[idx]);
        sm[OFF_WRK + o * 65 + c] = __ldg(&Wk[idx]);
    }
    __syncthreads();
    // transpose -> wct[c][80]: V(0..63) Q(64..71) K(72..79)
    for (int idx = tid; idx < CH * NOUT; idx += NTHREADS) {
        int c = idx / NOUT;
        int o = idx - c * NOUT;
        float v;
        if (o < 64)      v = sm[OFF_WRV + o * 65 + c];
        else if (o < 72) v = sm[OFF_WRQ + (o - 64) * 65 + c];
        else             v = sm[OFF_WRK + (o - 72) * 65 + c];
        sm[OFF_WCT + c * WCT_STRIDE + o] = v;
    }
    __syncthreads();

    // ===== Phase 1: fused 80-out projection, diag-packed f32x2 =====
    // 70 threads per window; tile = 8 tokens x 8 outs
    if (tid < 140) {
        const int win = (tid >= 70);
        const int r   = win ? tid - 70 : tid;
        const int og  = r % 10, tg = r / 10;
        const int o0  = og * 8, t0 = tg * 8;
        const float* xTp = sm + (win ? OFF_XT1 : OFF_XT0);

        u64 accA[4][4], accB[4][4];
        #pragma unroll
        for (int p = 0; p < 4; p++)
            #pragma unroll
            for (int q = 0; q < 4; q++) { accA[p][q] = 0ull; accB[p][q] = 0ull; }

        #pragma unroll 2
        for (int c = 0; c < CH; c++) {
            const u64* xr = reinterpret_cast<const u64*>(xTp + c * XT_STRIDE + t0);
            const u64* wr = reinterpret_cast<const u64*>(sm + OFF_WCT + c * WCT_STRIDE + o0);
            u64 xv[4];
            #pragma unroll
            for (int p = 0; p < 4; p++) xv[p] = xr[p];
            #pragma unroll
            for (int q = 0; q < 4; q++) {
                u64 wn = wr[q];
                u64 ws = f2swap(wn);
                #pragma unroll
                for (int p = 0; p < 4; p++) {
                    ffma2(accA[p][q], xv[p], wn);
                    ffma2(accB[p][q], xv[p], ws);
                }
            }
        }

        float bias[8];
        #pragma unroll
        for (int j = 0; j < 8; j++)
            bias[j] = (o0 < 64) ? __ldg(&bv[o0 + j])
                     : (o0 == 64 ? __ldg(&bq[j]) : __ldg(&bk[j]));

        float* vsp = sm + (win ? OFF_VS1 : OFF_VS0);
        float* qkp = sm + (o0 == 64 ? (win ? OFF_QS1 : OFF_QS0)
                                    : (win ? OFF_KS1 : OFF_KS0));
        #pragma unroll
        for (int p = 0; p < 4; p++) {
            int ta = t0 + 2 * p, tb = ta + 1;
            float oa[8], oc[8];
            #pragma unroll
            for (int q = 0; q < 4; q++) {
                oa[2*q]   = f2lo(accA[p][q]) + bias[2*q];
                oc[2*q+1] = f2hi(accA[p][q]) + bias[2*q+1];
                oa[2*q+1] = f2lo(accB[p][q]) + bias[2*q+1];
                oc[2*q]   = f2hi(accB[p][q]) + bias[2*q];
            }
            if (o0 < 64) {
                if (ta < NTOK) {
                    *reinterpret_cast<float4*>(vsp + ta*CH + o0)     = make_float4(oa[0],oa[1],oa[2],oa[3]);
                    *reinterpret_cast<float4*>(vsp + ta*CH + o0 + 4) = make_float4(oa[4],oa[5],oa[6],oa[7]);
                }
                if (tb < NTOK) {
                    *reinterpret_cast<float4*>(vsp + tb*CH + o0)     = make_float4(oc[0],oc[1],oc[2],oc[3]);
                    *reinterpret_cast<float4*>(vsp + tb*CH + o0 + 4) = make_float4(oc[4],oc[5],oc[6],oc[7]);
                }
            } else {
                *reinterpret_cast<float4*>(qkp + ta*8)     = make_float4(oa[0],oa[1],oa[2],oa[3]);
                *reinterpret_cast<float4*>(qkp + ta*8 + 4) = make_float4(oa[4],oa[5],oa[6],oa[7]);
                *reinterpret_cast<float4*>(qkp + tb*8)     = make_float4(oc[0],oc[1],oc[2],oc[3]);
                *reinterpret_cast<float4*>(qkp + tb*8 + 4) = make_float4(oc[4],oc[5],oc[6],oc[7]);
            }
        }
    }
    __syncthreads();

    // ===== Phase 2: logits -> attT[m][n] =====
    if (tid < 98) {
        const int win = (tid >= 49);
        const int r   = win ? tid - 49 : tid;
        const int n0  = (r / 7) * 7, m0 = (r % 7) * 7;
        const float* qp = sm + (win ? OFF_QS1 : OFF_QS0);
        const float* kp = sm + (win ? OFF_KS1 : OFF_KS0);
        float acc[7][7];
        #pragma unroll
        for (int i = 0; i < 7; i++)
            #pragma unroll
            for (int j = 0; j < 7; j++) acc[i][j] = 0.0f;
        #pragma unroll
        for (int c = 0; c < CQ; c++) {
            float qv[7], kv[7];
            #pragma unroll
            for (int i = 0; i < 7; i++) qv[i] = qp[(n0 + i) * 8 + c];
            #pragma unroll
            for (int j = 0; j < 7; j++) kv[j] = kp[(m0 + j) * 8 + c];
            #pragma unroll
            for (int i = 0; i < 7; i++)
                #pragma unroll
                for (int j = 0; j < 7; j++) acc[i][j] = fmaf(qv[i], kv[j], acc[i][j]);
        }
        float* atp = sm + (win ? OFF_AT1 : OFF_AT0);
        #pragma unroll
        for (int i = 0; i < 7; i++)
            #pragma unroll
            for (int j = 0; j < 7; j++)
                atp[(m0 + j) * AT_STRIDE + (n0 + i)] = acc[i][j];
    }
    __syncthreads();

    // ===== Phase 3: softmax over keys m (columns of attT) =====
    if (tid < 98) {
        const int win = (tid >= 49);
        const int n   = win ? tid - 49 : tid;
        float* atp = sm + (win ? OFF_AT1 : OFF_AT0) + n;
        float mx = atp[0];
        #pragma unroll 7
        for (int m = 1; m < NTOK; m++) mx = fmaxf(mx, atp[m * AT_STRIDE]);
        float s = 0.0f;
        #pragma unroll 7
        for (int m = 0; m < NTOK; m++) {
            float e = __expf(atp[m * AT_STRIDE] - mx);
            atp[m * AT_STRIDE] = e;
            s += e;
        }
        float rinv = 1.0f / s;
        #pragma unroll 7
        for (int m = 0; m < NTOK; m++) atp[m * AT_STRIDE] *= rinv;
    }
    __syncthreads();

    // ===== Phase 4: out = att @ V, diag-packed f32x2 =====
    u64 accA4[4][4], accB4[4][4];
    int p4_win = 0, p4_o0 = 0, p4_t0 = 0;
    if (tid < 112) {
        p4_win = (tid >= 56);
        const int r  = p4_win ? tid - 56 : tid;
        const int og = r % 8, tg = r / 8;
        p4_o0 = og * 8; p4_t0 = tg * 8;
        const float* atp = sm + (p4_win ? OFF_AT1 : OFF_AT0);
        const float* vp  = sm + (p4_win ? OFF_VS1 : OFF_VS0);

        #pragma unroll
        for (int p = 0; p < 4; p++)
            #pragma unroll
            for (int q = 0; q < 4; q++) { accA4[p][q] = 0ull; accB4[p][q] = 0ull; }

        #pragma unroll 2
        for (int m = 0; m < NTOK; m++) {
            const u64* ar = reinterpret_cast<const u64*>(atp + m * AT_STRIDE + p4_t0);
            const u64* vr = reinterpret_cast<const u64*>(vp + m * CH + p4_o0);
            u64 av[4];
            #pragma unroll
            for (int p = 0; p < 4; p++) av[p] = ar[p];
            #pragma unroll
            for (int q = 0; q < 4; q++) {
                u64 vn  = vr[q];
                u64 vsw = f2swap(vn);
                #pragma unroll
                for (int p = 0; p < 4; p++) {
                    ffma2(accA4[p][q], av[p], vn);
                    ffma2(accB4[p][q], av[p], vsw);
                }
            }
        }
    }
    __syncthreads();   // attT reads done before os overlays the pool

    if (tid < 112) {
        float* osp = sm + (p4_win ? OFF_POOL1 : OFF_POOL0);
        #pragma unroll
        for (int p = 0; p < 4; p++) {
            int ta = p4_t0 + 2 * p, tb = ta + 1;
            #pragma unroll
            for (int q = 0; q < 4; q++) {
                *reinterpret_cast<float2*>(osp + ta * OS_STRIDE + p4_o0 + 2*q)
                    = make_float2(f2lo(accA4[p][q]), f2lo(accB4[p][q]));
                *reinterpret_cast<float2*>(osp + tb * OS_STRIDE + p4_o0 + 2*q)
                    = make_float2(f2hi(accB4[p][q]), f2hi(accA4[p][q]));
            }
        }
    }
    __syncthreads();

    // ===== Phase 5: residual + coalesced store =====
    const float g = __ldg(gamma);
    float* ob = out + (size_t)b * CH * HWDIM * HWDIM;
    for (int idx = tid; idx < CH * WS * 14; idx += NTHREADS) {
        int c  = idx / 98;
        int r  = idx - c * 98;
        int ph = r / 14;
        int pw = r - ph * 14;
        int win = (pw >= 7);
        int t  = ph * 7 + (pw - win * 7);
        float o_v = sm[(win ? OFF_POOL1 : OFF_POOL0) + t * OS_STRIDE + c];
        float x_v = sm[(win ? OFF_XT1 : OFF_XT0) + c * XT_STRIDE + t];
        ob[((size_t)c * HWDIM + (h0 + ph)) * HWDIM + (w0 + pw)] = fmaf(g, o_v, x_v);
    }
}

extern "C" void kernel_launch(void* const* d_in, const int* in_sizes, int n_in,
                              void* d_out, int out_size)
{
    const float* x     = (const float*)d_in[0];
    const float* Wq    = (const float*)d_in[1];
    const float* bq    = (const float*)d_in[2];
    const float* Wk    = (const float*)d_in[3];
    const float* bk    = (const float*)d_in[4];
    const float* Wv    = (const float*)d_in[5];
    const float* bv    = (const float*)d_in[6];
    const float* gamma = (const float*)d_in[7];
    float* out = (float*)d_out;

    cudaFuncSetAttribute(lattn_kernel, cudaFuncAttributeMaxDynamicSharedMemorySize, SMEM_BYTES);

    dim3 grid(16 * 32 * 16);   // batch * window-rows * window-pairs
    lattn_kernel<<<grid, NTHREADS, SMEM_BYTES>>>(x, Wq, bq, Wk, bk, Wv, bv, gamma, out);
}